// round 13
// baseline (speedup 1.0000x reference)
#include <cuda_runtime.h>
#include <math.h>
#include <stdint.h>

// Problem dims
#define T_STEPS 8192
#define IN_DIM  2048
#define H_DIM   1024
#define G4      4096   // 4*H
#define MID_DIM 128

// ---------------- persistent device scratch (no allocations allowed) -------
__device__ float g_xw[(size_t)T_STEPS * G4];     // 128 MB: precomputed x @ W_ih^T + b_ih + b_hh
__device__ float g_h[2][H_DIM];                  // double-buffered hidden state
__device__ unsigned g_bar_count = 0;
__device__ unsigned g_bar_gen   = 0;

// ---------------- recurrence kernel config --------------------------------
#define NBLK     128          // persistent CTAs (<=148 SMs, 1/SM due to smem)
#define UNITS    8            // hidden units per CTA  (128*8 = 1024)
#define RROWS    32           // 4 gates * UNITS rows of W_hh per CTA
#define RTHREADS 256
// dyn smem: W slice [32][1024] + h [1024] + gate dots [32] + c [8]
#define RSMEM_FLOATS (RROWS*H_DIM + H_DIM + RROWS + UNITS)
#define RSMEM_BYTES  (RSMEM_FLOATS * 4)

__device__ __forceinline__ void grid_barrier() {
    __syncthreads();
    if (threadIdx.x == 0) {
        unsigned gen = *(volatile unsigned*)&g_bar_gen;   // snapshot BEFORE arriving
        __threadfence();
        if (atomicAdd(&g_bar_count, 1u) == NBLK - 1) {
            atomicExch(&g_bar_count, 0u);
            __threadfence();
            atomicAdd(&g_bar_gen, 1u);
        } else {
            volatile unsigned* vg = &g_bar_gen;
            while (*vg == gen) { }
            __threadfence();
        }
    }
    __syncthreads();
}

__device__ __forceinline__ float sigmoidf_(float x) {
    return 1.0f / (1.0f + expf(-x));
}

// ---------------------------------------------------------------------------
// Kernel 1: xW = x_seq @ W_ih^T + (b_ih + b_hh)   [8192 x 4096], K = 2048
// classic 128x128 tile, BK=16, 256 threads, 8x8 per thread, fp32
// ---------------------------------------------------------------------------
#define BM 128
#define BN 128
#define BK 16

__global__ void __launch_bounds__(256) gemm_xw_kernel(
    const float* __restrict__ A,      // x_seq  [8192][2048]
    const float* __restrict__ B,      // W_ih   [4096][2048]
    const float* __restrict__ b_ih,
    const float* __restrict__ b_hh)
{
    __shared__ float As[BK][BM];
    __shared__ float Bs[BK][BN];

    const int tid = threadIdx.x;        // 0..255
    const int tx  = tid & 15;
    const int ty  = tid >> 4;
    const int m0  = blockIdx.y * BM;
    const int n0  = blockIdx.x * BN;

    float acc[8][8];
    #pragma unroll
    for (int i = 0; i < 8; i++)
        #pragma unroll
        for (int j = 0; j < 8; j++) acc[i][j] = 0.0f;

    for (int k0 = 0; k0 < IN_DIM; k0 += BK) {
        // load A tile (transposed into smem): 128 rows x 16 k
        #pragma unroll
        for (int l = 0; l < 2; l++) {
            int li  = tid + l * 256;          // 0..511
            int row = li >> 2;
            int kv  = li & 3;
            float4 a = *(const float4*)(A + (size_t)(m0 + row) * IN_DIM + k0 + kv * 4);
            As[kv * 4 + 0][row] = a.x;
            As[kv * 4 + 1][row] = a.y;
            As[kv * 4 + 2][row] = a.z;
            As[kv * 4 + 3][row] = a.w;
        }
        // load B tile (W_ih rows = output cols), transposed into smem
        #pragma unroll
        for (int l = 0; l < 2; l++) {
            int li  = tid + l * 256;
            int row = li >> 2;
            int kv  = li & 3;
            float4 b = *(const float4*)(B + (size_t)(n0 + row) * IN_DIM + k0 + kv * 4);
            Bs[kv * 4 + 0][row] = b.x;
            Bs[kv * 4 + 1][row] = b.y;
            Bs[kv * 4 + 2][row] = b.z;
            Bs[kv * 4 + 3][row] = b.w;
        }
        __syncthreads();

        #pragma unroll
        for (int k = 0; k < BK; k++) {
            float a[8], b[8];
            *(float4*)&a[0] = *(const float4*)&As[k][ty * 8];
            *(float4*)&a[4] = *(const float4*)&As[k][ty * 8 + 4];
            *(float4*)&b[0] = *(const float4*)&Bs[k][tx * 8];
            *(float4*)&b[4] = *(const float4*)&Bs[k][tx * 8 + 4];
            #pragma unroll
            for (int i = 0; i < 8; i++)
                #pragma unroll
                for (int j = 0; j < 8; j++)
                    acc[i][j] += a[i] * b[j];
        }
        __syncthreads();
    }

    // bias + store
    float bias[8];
    #pragma unroll
    for (int j = 0; j < 8; j++) {
        int n = n0 + tx * 8 + j;
        bias[j] = b_ih[n] + b_hh[n];
    }
    #pragma unroll
    for (int i = 0; i < 8; i++) {
        int m = m0 + ty * 8 + i;
        float4 v0 = make_float4(acc[i][0] + bias[0], acc[i][1] + bias[1],
                                acc[i][2] + bias[2], acc[i][3] + bias[3]);
        float4 v1 = make_float4(acc[i][4] + bias[4], acc[i][5] + bias[5],
                                acc[i][6] + bias[6], acc[i][7] + bias[7]);
        float* crow = g_xw + (size_t)m * G4 + n0 + tx * 8;
        *(float4*)(crow)     = v0;
        *(float4*)(crow + 4) = v1;
    }
}

// ---------------------------------------------------------------------------
// Kernel 2: persistent LSTM recurrence. 128 CTAs, W_hh slice in SMEM.
// CTA b owns hidden units [b*8, b*8+8). Row-local rl = gate*8 + unit.
// ---------------------------------------------------------------------------
extern __shared__ float rnn_sm[];

__global__ void __launch_bounds__(RTHREADS, 1) lstm_rnn_kernel(
    const float* __restrict__ W_hh)   // [4096][1024]
{
    float* sW = rnn_sm;                        // [32][1024]
    float* sh = rnn_sm + RROWS * H_DIM;        // [1024]
    float* sg = sh + H_DIM;                    // [32]
    float* sc = sg + RROWS;                    // [8]

    const int tid = threadIdx.x;
    const int b   = blockIdx.x;
    const int ub  = b * UNITS;

    // stage this CTA's W_hh slice into shared memory (once)
    for (int idx = tid; idx < RROWS * (H_DIM / 4); idx += RTHREADS) {
        int rl = idx >> 8;                     // /256 float4 per row
        int kv = idx & 255;
        int grow = (rl >> 3) * H_DIM + ub + (rl & 7);
        float4 wv = *(const float4*)(W_hh + (size_t)grow * H_DIM + kv * 4);
        *(float4*)(sW + rl * H_DIM + kv * 4) = wv;
    }
    if (tid < UNITS) {
        sc[tid] = 0.0f;
        g_h[0][ub + tid] = 0.0f;               // h0 = 0
    }
    grid_barrier();                            // all h0 slices visible

    const int w    = tid >> 5;                 // warp 0..7 -> rows w*4..w*4+3
    const int lane = tid & 31;
    const float4* r0 = (const float4*)(sW + (w * 4 + 0) * H_DIM);
    const float4* r1 = (const float4*)(sW + (w * 4 + 1) * H_DIM);
    const float4* r2 = (const float4*)(sW + (w * 4 + 2) * H_DIM);
    const float4* r3 = (const float4*)(sW + (w * 4 + 3) * H_DIM);
    const float4* sh4 = (const float4*)sh;

    for (int t = 0; t < T_STEPS; t++) {
        // prefetch this CTA's 32 xW gate values early (hides DRAM latency)
        float xwv0 = 0.f, xwv1 = 0.f, xwv2 = 0.f, xwv3 = 0.f;
        if (tid < UNITS) {
            const float* xp = g_xw + (size_t)t * G4 + ub + tid;
            xwv0 = __ldg(xp);
            xwv1 = __ldg(xp + H_DIM);
            xwv2 = __ldg(xp + 2 * H_DIM);
            xwv3 = __ldg(xp + 3 * H_DIM);
        }

        // load h_prev (bypass L1: written by other SMs last step)
        {
            const float4* hb = (const float4*)g_h[t & 1];
            float4 hv = __ldcg(hb + tid);      // 256 * float4 = 1024 floats
            *(float4*)(sh + tid * 4) = hv;
        }
        __syncthreads();

        // 4 dot products per warp over K=1024 (256 float4, lane-strided)
        float a0 = 0.f, a1 = 0.f, a2 = 0.f, a3 = 0.f;
        #pragma unroll
        for (int it = 0; it < 8; it++) {
            int kv = lane + it * 32;
            float4 h4 = sh4[kv];
            float4 w0 = r0[kv];
            float4 w1 = r1[kv];
            float4 w2 = r2[kv];
            float4 w3 = r3[kv];
            a0 += h4.x * w0.x + h4.y * w0.y + h4.z * w0.z + h4.w * w0.w;
            a1 += h4.x * w1.x + h4.y * w1.y + h4.z * w1.z + h4.w * w1.w;
            a2 += h4.x * w2.x + h4.y * w2.y + h4.z * w2.z + h4.w * w2.w;
            a3 += h4.x * w3.x + h4.y * w3.y + h4.z * w3.z + h4.w * w3.w;
        }
        #pragma unroll
        for (int off = 16; off > 0; off >>= 1) {
            a0 += __shfl_down_sync(0xffffffffu, a0, off);
            a1 += __shfl_down_sync(0xffffffffu, a1, off);
            a2 += __shfl_down_sync(0xffffffffu, a2, off);
            a3 += __shfl_down_sync(0xffffffffu, a3, off);
        }
        if (lane == 0) {
            sg[w * 4 + 0] = a0;
            sg[w * 4 + 1] = a1;
            sg[w * 4 + 2] = a2;
            sg[w * 4 + 3] = a3;
        }
        __syncthreads();

        // gate math + state update for this CTA's 8 hidden units
        if (tid < UNITS) {
            int u = tid;
            float gi = xwv0 + sg[0 * UNITS + u];
            float gf = xwv1 + sg[1 * UNITS + u];
            float gg = xwv2 + sg[2 * UNITS + u];
            float go = xwv3 + sg[3 * UNITS + u];
            float iv = sigmoidf_(gi);
            float fv = sigmoidf_(gf);
            float gv = tanhf(gg);
            float ov = sigmoidf_(go);
            float c  = fv * sc[u] + iv * gv;
            sc[u] = c;
            g_h[(t + 1) & 1][ub + u] = ov * tanhf(c);
        }
        grid_barrier();
    }
}

// ---------------------------------------------------------------------------
// Kernel 3: classifier: out = sigmoid( relu(h_T @ W1^T + b1) @ W2^T + b2 )
// h_T lives in g_h[0] (T even). Single block.
// ---------------------------------------------------------------------------
__global__ void __launch_bounds__(256) classifier_kernel(
    const float* __restrict__ W1,   // [128][1024]
    const float* __restrict__ b1,   // [128]
    const float* __restrict__ W2,   // [128]
    const float* __restrict__ b2,   // [1]
    float* __restrict__ out)
{
    __shared__ float sh[H_DIM];
    __shared__ float shid[MID_DIM];

    const int tid  = threadIdx.x;   // 256
    const int w    = tid >> 5;
    const int lane = tid & 31;

    *(float4*)(sh + tid * 4) = *(const float4*)(&g_h[0][tid * 4]);
    __syncthreads();

    // 8 warps x 16 rows
    for (int r = w * 16; r < w * 16 + 16; r++) {
        float a = 0.0f;
        for (int k = lane; k < H_DIM; k += 32)
            a += W1[r * H_DIM + k] * sh[k];
        #pragma unroll
        for (int off = 16; off > 0; off >>= 1)
            a += __shfl_down_sync(0xffffffffu, a, off);
        if (lane == 0)
            shid[r] = fmaxf(a + b1[r], 0.0f);
    }
    __syncthreads();

    if (w == 0) {
        float a = 0.0f;
        #pragma unroll
        for (int m = lane; m < MID_DIM; m += 32)
            a += shid[m] * W2[m];
        #pragma unroll
        for (int off = 16; off > 0; off >>= 1)
            a += __shfl_down_sync(0xffffffffu, a, off);
        if (lane == 0)
            out[0] = 1.0f / (1.0f + expf(-(a + b2[0])));
    }
}

// ---------------------------------------------------------------------------
extern "C" void kernel_launch(void* const* d_in, const int* in_sizes, int n_in,
                              void* d_out, int out_size)
{
    const float* x    = (const float*)d_in[0];   // [8192,2048]
    const float* W_ih = (const float*)d_in[1];   // [4096,2048]
    const float* W_hh = (const float*)d_in[2];   // [4096,1024]
    const float* b_ih = (const float*)d_in[3];   // [4096]
    const float* b_hh = (const float*)d_in[4];   // [4096]
    const float* W1   = (const float*)d_in[5];   // [128,1024]
    const float* b1   = (const float*)d_in[6];   // [128]
    const float* W2   = (const float*)d_in[7];   // [128]
    const float* b2   = (const float*)d_in[8];   // [1]
    float* out = (float*)d_out;

    // opt in to >48KB dynamic smem for the persistent recurrence kernel
    cudaFuncSetAttribute(lstm_rnn_kernel,
                         cudaFuncAttributeMaxDynamicSharedMemorySize,
                         RSMEM_BYTES);

    dim3 gemm_grid(G4 / BN, T_STEPS / BM);       // (32, 64)
    gemm_xw_kernel<<<gemm_grid, 256>>>(x, W_ih, b_ih, b_hh);

    lstm_rnn_kernel<<<NBLK, RTHREADS, RSMEM_BYTES>>>(W_hh);

    classifier_kernel<<<1, 256>>>(W1, b1, W2, b2, out);
}

// round 14
// speedup vs baseline: 1.0006x; 1.0006x over previous
#include <cuda_runtime.h>
#include <math.h>
#include <stdint.h>

// Problem dims
#define T_STEPS 8192
#define IN_DIM  2048
#define H_DIM   1024
#define G4      4096   // 4*H
#define MID_DIM 128

// ---------------- persistent device scratch (no allocations allowed) -------
__device__ float g_xw[(size_t)T_STEPS * G4];     // 128 MB: precomputed x @ W_ih^T + b_ih + b_hh
__device__ float g_h[2][H_DIM];                  // double-buffered hidden state
__device__ unsigned g_bar_count = 0;
__device__ unsigned g_bar_gen   = 0;

// ---------------- recurrence kernel config --------------------------------
#define NBLK     128          // persistent CTAs (<=148 SMs, 1/SM due to smem)
#define UNITS    8            // hidden units per CTA  (128*8 = 1024)
#define RROWS    32           // 4 gates * UNITS rows of W_hh per CTA
#define RTHREADS 256
// dyn smem: W slice [32][1024] + h [1024] + gate dots [32] + c [8]
#define RSMEM_FLOATS (RROWS*H_DIM + H_DIM + RROWS + UNITS)
#define RSMEM_BYTES  (RSMEM_FLOATS * 4)

__device__ __forceinline__ void grid_barrier() {
    __syncthreads();
    if (threadIdx.x == 0) {
        unsigned gen = *(volatile unsigned*)&g_bar_gen;   // snapshot BEFORE arriving
        __threadfence();
        if (atomicAdd(&g_bar_count, 1u) == NBLK - 1) {
            atomicExch(&g_bar_count, 0u);
            __threadfence();
            atomicAdd(&g_bar_gen, 1u);
        } else {
            volatile unsigned* vg = &g_bar_gen;
            while (*vg == gen) { }
            __threadfence();
        }
    }
    __syncthreads();
}

__device__ __forceinline__ float sigmoidf_(float x) {
    return 1.0f / (1.0f + expf(-x));
}

// ---------------------------------------------------------------------------
// Kernel 1: xW = x_seq @ W_ih^T + (b_ih + b_hh)   [8192 x 4096], K = 2048
// classic 128x128 tile, BK=16, 256 threads, 8x8 per thread, fp32
// ---------------------------------------------------------------------------
#define BM 128
#define BN 128
#define BK 16

__global__ void __launch_bounds__(256) gemm_xw_kernel(
    const float* __restrict__ A,      // x_seq  [8192][2048]
    const float* __restrict__ B,      // W_ih   [4096][2048]
    const float* __restrict__ b_ih,
    const float* __restrict__ b_hh)
{
    __shared__ float As[BK][BM];
    __shared__ float Bs[BK][BN];

    const int tid = threadIdx.x;        // 0..255
    const int tx  = tid & 15;
    const int ty  = tid >> 4;
    const int m0  = blockIdx.y * BM;
    const int n0  = blockIdx.x * BN;

    float acc[8][8];
    #pragma unroll
    for (int i = 0; i < 8; i++)
        #pragma unroll
        for (int j = 0; j < 8; j++) acc[i][j] = 0.0f;

    for (int k0 = 0; k0 < IN_DIM; k0 += BK) {
        // load A tile (transposed into smem): 128 rows x 16 k
        #pragma unroll
        for (int l = 0; l < 2; l++) {
            int li  = tid + l * 256;          // 0..511
            int row = li >> 2;
            int kv  = li & 3;
            float4 a = *(const float4*)(A + (size_t)(m0 + row) * IN_DIM + k0 + kv * 4);
            As[kv * 4 + 0][row] = a.x;
            As[kv * 4 + 1][row] = a.y;
            As[kv * 4 + 2][row] = a.z;
            As[kv * 4 + 3][row] = a.w;
        }
        // load B tile (W_ih rows = output cols), transposed into smem
        #pragma unroll
        for (int l = 0; l < 2; l++) {
            int li  = tid + l * 256;
            int row = li >> 2;
            int kv  = li & 3;
            float4 b = *(const float4*)(B + (size_t)(n0 + row) * IN_DIM + k0 + kv * 4);
            Bs[kv * 4 + 0][row] = b.x;
            Bs[kv * 4 + 1][row] = b.y;
            Bs[kv * 4 + 2][row] = b.z;
            Bs[kv * 4 + 3][row] = b.w;
        }
        __syncthreads();

        #pragma unroll
        for (int k = 0; k < BK; k++) {
            float a[8], b[8];
            *(float4*)&a[0] = *(const float4*)&As[k][ty * 8];
            *(float4*)&a[4] = *(const float4*)&As[k][ty * 8 + 4];
            *(float4*)&b[0] = *(const float4*)&Bs[k][tx * 8];
            *(float4*)&b[4] = *(const float4*)&Bs[k][tx * 8 + 4];
            #pragma unroll
            for (int i = 0; i < 8; i++)
                #pragma unroll
                for (int j = 0; j < 8; j++)
                    acc[i][j] += a[i] * b[j];
        }
        __syncthreads();
    }

    // bias + store
    float bias[8];
    #pragma unroll
    for (int j = 0; j < 8; j++) {
        int n = n0 + tx * 8 + j;
        bias[j] = b_ih[n] + b_hh[n];
    }
    #pragma unroll
    for (int i = 0; i < 8; i++) {
        int m = m0 + ty * 8 + i;
        float4 v0 = make_float4(acc[i][0] + bias[0], acc[i][1] + bias[1],
                                acc[i][2] + bias[2], acc[i][3] + bias[3]);
        float4 v1 = make_float4(acc[i][4] + bias[4], acc[i][5] + bias[5],
                                acc[i][6] + bias[6], acc[i][7] + bias[7]);
        float* crow = g_xw + (size_t)m * G4 + n0 + tx * 8;
        *(float4*)(crow)     = v0;
        *(float4*)(crow + 4) = v1;
    }
}

// ---------------------------------------------------------------------------
// Kernel 2: persistent LSTM recurrence. 128 CTAs, W_hh slice in SMEM.
// CTA b owns hidden units [b*8, b*8+8). Row-local rl = gate*8 + unit.
// ---------------------------------------------------------------------------
extern __shared__ float rnn_sm[];

__global__ void __launch_bounds__(RTHREADS, 1) lstm_rnn_kernel(
    const float* __restrict__ W_hh)   // [4096][1024]
{
    float* sW = rnn_sm;                        // [32][1024]
    float* sh = rnn_sm + RROWS * H_DIM;        // [1024]
    float* sg = sh + H_DIM;                    // [32]
    float* sc = sg + RROWS;                    // [8]

    const int tid = threadIdx.x;
    const int b   = blockIdx.x;
    const int ub  = b * UNITS;

    // stage this CTA's W_hh slice into shared memory (once)
    for (int idx = tid; idx < RROWS * (H_DIM / 4); idx += RTHREADS) {
        int rl = idx >> 8;                     // /256 float4 per row
        int kv = idx & 255;
        int grow = (rl >> 3) * H_DIM + ub + (rl & 7);
        float4 wv = *(const float4*)(W_hh + (size_t)grow * H_DIM + kv * 4);
        *(float4*)(sW + rl * H_DIM + kv * 4) = wv;
    }
    if (tid < UNITS) {
        sc[tid] = 0.0f;
        g_h[0][ub + tid] = 0.0f;               // h0 = 0
    }
    grid_barrier();                            // all h0 slices visible

    const int w    = tid >> 5;                 // warp 0..7 -> rows w*4..w*4+3
    const int lane = tid & 31;
    const float4* r0 = (const float4*)(sW + (w * 4 + 0) * H_DIM);
    const float4* r1 = (const float4*)(sW + (w * 4 + 1) * H_DIM);
    const float4* r2 = (const float4*)(sW + (w * 4 + 2) * H_DIM);
    const float4* r3 = (const float4*)(sW + (w * 4 + 3) * H_DIM);
    const float4* sh4 = (const float4*)sh;

    for (int t = 0; t < T_STEPS; t++) {
        // prefetch this CTA's 32 xW gate values early (hides DRAM latency)
        float xwv0 = 0.f, xwv1 = 0.f, xwv2 = 0.f, xwv3 = 0.f;
        if (tid < UNITS) {
            const float* xp = g_xw + (size_t)t * G4 + ub + tid;
            xwv0 = __ldg(xp);
            xwv1 = __ldg(xp + H_DIM);
            xwv2 = __ldg(xp + 2 * H_DIM);
            xwv3 = __ldg(xp + 3 * H_DIM);
        }

        // load h_prev (bypass L1: written by other SMs last step)
        {
            const float4* hb = (const float4*)g_h[t & 1];
            float4 hv = __ldcg(hb + tid);      // 256 * float4 = 1024 floats
            *(float4*)(sh + tid * 4) = hv;
        }
        __syncthreads();

        // 4 dot products per warp over K=1024 (256 float4, lane-strided)
        float a0 = 0.f, a1 = 0.f, a2 = 0.f, a3 = 0.f;
        #pragma unroll
        for (int it = 0; it < 8; it++) {
            int kv = lane + it * 32;
            float4 h4 = sh4[kv];
            float4 w0 = r0[kv];
            float4 w1 = r1[kv];
            float4 w2 = r2[kv];
            float4 w3 = r3[kv];
            a0 += h4.x * w0.x + h4.y * w0.y + h4.z * w0.z + h4.w * w0.w;
            a1 += h4.x * w1.x + h4.y * w1.y + h4.z * w1.z + h4.w * w1.w;
            a2 += h4.x * w2.x + h4.y * w2.y + h4.z * w2.z + h4.w * w2.w;
            a3 += h4.x * w3.x + h4.y * w3.y + h4.z * w3.z + h4.w * w3.w;
        }
        #pragma unroll
        for (int off = 16; off > 0; off >>= 1) {
            a0 += __shfl_down_sync(0xffffffffu, a0, off);
            a1 += __shfl_down_sync(0xffffffffu, a1, off);
            a2 += __shfl_down_sync(0xffffffffu, a2, off);
            a3 += __shfl_down_sync(0xffffffffu, a3, off);
        }
        if (lane == 0) {
            sg[w * 4 + 0] = a0;
            sg[w * 4 + 1] = a1;
            sg[w * 4 + 2] = a2;
            sg[w * 4 + 3] = a3;
        }
        __syncthreads();

        // gate math + state update for this CTA's 8 hidden units
        if (tid < UNITS) {
            int u = tid;
            float gi = xwv0 + sg[0 * UNITS + u];
            float gf = xwv1 + sg[1 * UNITS + u];
            float gg = xwv2 + sg[2 * UNITS + u];
            float go = xwv3 + sg[3 * UNITS + u];
            float iv = sigmoidf_(gi);
            float fv = sigmoidf_(gf);
            float gv = tanhf(gg);
            float ov = sigmoidf_(go);
            float c  = fv * sc[u] + iv * gv;
            sc[u] = c;
            g_h[(t + 1) & 1][ub + u] = ov * tanhf(c);
        }
        grid_barrier();
    }
}

// ---------------------------------------------------------------------------
// Kernel 3: classifier: out = sigmoid( relu(h_T @ W1^T + b1) @ W2^T + b2 )
// h_T lives in g_h[0] (T even). Single block.
// ---------------------------------------------------------------------------
__global__ void __launch_bounds__(256) classifier_kernel(
    const float* __restrict__ W1,   // [128][1024]
    const float* __restrict__ b1,   // [128]
    const float* __restrict__ W2,   // [128]
    const float* __restrict__ b2,   // [1]
    float* __restrict__ out)
{
    __shared__ float sh[H_DIM];
    __shared__ float shid[MID_DIM];

    const int tid  = threadIdx.x;   // 256
    const int w    = tid >> 5;
    const int lane = tid & 31;

    *(float4*)(sh + tid * 4) = *(const float4*)(&g_h[0][tid * 4]);
    __syncthreads();

    // 8 warps x 16 rows
    for (int r = w * 16; r < w * 16 + 16; r++) {
        float a = 0.0f;
        for (int k = lane; k < H_DIM; k += 32)
            a += W1[r * H_DIM + k] * sh[k];
        #pragma unroll
        for (int off = 16; off > 0; off >>= 1)
            a += __shfl_down_sync(0xffffffffu, a, off);
        if (lane == 0)
            shid[r] = fmaxf(a + b1[r], 0.0f);
    }
    __syncthreads();

    if (w == 0) {
        float a = 0.0f;
        #pragma unroll
        for (int m = lane; m < MID_DIM; m += 32)
            a += shid[m] * W2[m];
        #pragma unroll
        for (int off = 16; off > 0; off >>= 1)
            a += __shfl_down_sync(0xffffffffu, a, off);
        if (lane == 0)
            out[0] = 1.0f / (1.0f + expf(-(a + b2[0])));
    }
}

// ---------------------------------------------------------------------------
extern "C" void kernel_launch(void* const* d_in, const int* in_sizes, int n_in,
                              void* d_out, int out_size)
{
    const float* x    = (const float*)d_in[0];   // [8192,2048]
    const float* W_ih = (const float*)d_in[1];   // [4096,2048]
    const float* W_hh = (const float*)d_in[2];   // [4096,1024]
    const float* b_ih = (const float*)d_in[3];   // [4096]
    const float* b_hh = (const float*)d_in[4];   // [4096]
    const float* W1   = (const float*)d_in[5];   // [128,1024]
    const float* b1   = (const float*)d_in[6];   // [128]
    const float* W2   = (const float*)d_in[7];   // [128]
    const float* b2   = (const float*)d_in[8];   // [1]
    float* out = (float*)d_out;

    // opt in to >48KB dynamic smem for the persistent recurrence kernel
    cudaFuncSetAttribute(lstm_rnn_kernel,
                         cudaFuncAttributeMaxDynamicSharedMemorySize,
                         RSMEM_BYTES);

    dim3 gemm_grid(G4 / BN, T_STEPS / BM);       // (32, 64)
    gemm_xw_kernel<<<gemm_grid, 256>>>(x, W_ih, b_ih, b_hh);

    lstm_rnn_kernel<<<NBLK, RTHREADS, RSMEM_BYTES>>>(W_hh);

    classifier_kernel<<<1, 256>>>(W1, b1, W2, b2, out);
}